// round 12
// baseline (speedup 1.0000x reference)
#include <cuda_runtime.h>
#include <cuda_bf16.h>

// ---------------------------------------------------------------------------
// NeuralODE Dopri5, R12: warp-private rows, ZERO loop barriers.
//  - 128 thr / 4 warps per CTA, grid 128; each warp owns 16 rows end-to-end.
//  - C-frag(GEMM1) == A-frag(GEMM2) register identity: H never leaves regs.
//  - build_arg produces GEMM1 A-frags in regs from y/kp (smem, own-slot,
//    conflict-free, no sync). Weights W1t/W2t read via ldmatrix per GEMM.
//  - Only barriers: 2x __syncthreads at init.
// ---------------------------------------------------------------------------

#define PADK 136                        // bf16 row stride: conflict-free ldsm
typedef __nv_bfloat16 Row[PADK];

__device__ float g_dt0;

__device__ __forceinline__ unsigned cvt_bf2u(float lo, float hi) {
    unsigned r; asm("cvt.rn.bf16x2.f32 %0, %1, %2;" : "=r"(r) : "f"(hi), "f"(lo)); return r;
}
__device__ __forceinline__ unsigned tanh_bf2(unsigned p) {
    unsigned r; asm("tanh.approx.bf16x2 %0, %1;" : "=r"(r) : "r"(p)); return r;
}
__device__ __forceinline__ float lo16f(unsigned u) { return __uint_as_float(u << 16); }
__device__ __forceinline__ float hi16f(unsigned u) { return __uint_as_float(u & 0xFFFF0000u); }
__device__ __forceinline__ __nv_bfloat162 asbf2(unsigned u) {
    return *reinterpret_cast<__nv_bfloat162*>(&u);
}
__device__ __forceinline__ void mma_bf16(float* c, const unsigned* a, const unsigned* b) {
    asm volatile("mma.sync.aligned.m16n8k16.row.col.f32.bf16.bf16.f32 "
                 "{%0,%1,%2,%3}, {%4,%5,%6,%7}, {%8,%9}, {%0,%1,%2,%3};"
                 : "+f"(c[0]), "+f"(c[1]), "+f"(c[2]), "+f"(c[3])
                 : "r"(a[0]), "r"(a[1]), "r"(a[2]), "r"(a[3]), "r"(b[0]), "r"(b[1]));
}
__device__ __forceinline__ void ldsm_x4(unsigned a[4], unsigned addr) {
    asm volatile("ldmatrix.sync.aligned.m8n8.x4.shared.b16 {%0,%1,%2,%3}, [%4];"
                 : "=r"(a[0]), "=r"(a[1]), "=r"(a[2]), "=r"(a[3]) : "r"(addr));
}

// C[16x128] = A(frags in regs)[16x128] @ Wt^T + bias. B via ldmatrix.
__device__ __forceinline__ void gemm128(float c[16][4], const unsigned aH[8][4],
                                        unsigned Bbase, const float* bias, int qn) {
#pragma unroll
    for (int nt = 0; nt < 16; nt++) {
        const int nb = nt * 8 + qn * 2;
        float b0 = bias[nb], b1 = bias[nb + 1];
        c[nt][0] = c[nt][2] = b0;
        c[nt][1] = c[nt][3] = b1;
    }
#pragma unroll
    for (int kk = 0; kk < 8; kk++) {
        unsigned b[8][4];
#pragma unroll
        for (int g = 0; g < 8; g++)
            ldsm_x4(b[g], Bbase + g * (16 * PADK * 2) + kk * 32);
#pragma unroll
        for (int g = 0; g < 8; g++) {
            mma_bf16(c[2 * g],     aH[kk], b[g]);
            mma_bf16(c[2 * g + 1], aH[kk], b[g] + 2);
        }
    }
}

// arg A-frags from y (fp32 smem) + dt * combo(kp bf16x2 smem). Own-slot only.
template <int NK>
__device__ __forceinline__ void build_arg(unsigned aH[8][4],
                                          const float2* y2, const unsigned* kpb,
                                          float dt, const __nv_bfloat162* kc) {
#pragma unroll
    for (int nt = 0; nt < 16; nt++)
#pragma unroll
        for (int h = 0; h < 2; h++) {
            const int slot = (nt * 2 + h) * 32;   // lane offset added via pointer
            float2 yv = y2[slot];
            float a0 = yv.x, a1 = yv.y;
            if (NK > 0) {
                __nv_bfloat162 acc = __hmul2(asbf2(kpb[0 * 4096 + slot]), kc[0]);
#pragma unroll
                for (int q = 1; q < NK; q++)
                    acc = __hfma2(asbf2(kpb[q * 4096 + slot]), kc[q], acc);
                unsigned au = *reinterpret_cast<unsigned*>(&acc);
                a0 = fmaf(dt, lo16f(au), a0);
                a1 = fmaf(dt, hi16f(au), a1);
            }
            aH[nt >> 1][(nt & 1) * 2 + h] = cvt_bf2u(a0, a1);
        }
}

__global__ void __launch_bounds__(128, 1)
ode_kernel(const float* __restrict__ t, const float* __restrict__ x,
           const float* __restrict__ W1, const float* __restrict__ b1,
           const float* __restrict__ W2, const float* __restrict__ b2,
           float* __restrict__ out) {
    extern __shared__ unsigned char raw[];
    // smem: W1t | W2t | bias(256 f32) | y2 (64x128 fp32, frag layout) | kp[5]
    Row*   W1st  = (Row*)raw;
    Row*   W2st  = (Row*)(raw + 34816);
    float* bstag = (float*)(raw + 69632);
    float2* y2all = (float2*)(raw + 70656);            // 4096 float2 = 32768 B
    unsigned* kpall = (unsigned*)(raw + 103424);       // 5*4096 u32 = 81920 B

    const int tid  = threadIdx.x;
    const int row0 = blockIdx.x * 64;
    const int lane = tid & 31, warp = tid >> 5;
    const int gm = lane >> 2, qn = lane & 3;

    // ---- stage weights (transposed bf16) + biases ----
    for (int idx = tid; idx < 128 * 128; idx += 128) {
        int k = idx >> 7, n = idx & 127;
        W1st[n][k] = __float2bfloat16(W1[idx]);
        W2st[n][k] = __float2bfloat16(W2[idx]);
    }
    if (tid < 128) { bstag[tid] = b1[tid]; bstag[128 + tid] = b2[tid]; }
    // x -> y2 (frag layout) + out[0] copy. idx over float2 pairs.
    for (int idx = tid; idx < 64 * 64; idx += 128) {
        int row = idx >> 6, cp = idx & 63;           // col = 2*cp
        float2 v = *(const float2*)&x[(row0 + row) * 128 + cp * 2];
        *(float2*)&out[(row0 + row) * 128 + cp * 2] = v;
        int w = row >> 4, h = (row >> 3) & 1, g = row & 7;
        int nt = cp >> 2, q = cp & 3;
        y2all[w * 1024 + (nt * 2 + h) * 32 + g * 4 + q] = v;
    }
    __syncthreads();

    const float T   = t[0] / 10.0f;    // TIMESCALE = 10
    const float dt0 = g_dt0;

    // per-thread smem views (own slot set; + lane offset baked in)
    float2*   y2  = y2all + warp * 1024 + lane;
    unsigned* kpb = kpall + warp * 1024 + lane;

    // B ldmatrix lane mapping (proven in prior rounds)
    const int browoff = (lane & 7) + ((lane >> 4) << 3);
    const int bcoloff = ((lane >> 3) & 1) * 8;
    const unsigned B1b_ = (unsigned)__cvta_generic_to_shared(W1st)
                        + (unsigned)((browoff * PADK + bcoloff) * 2);
    const unsigned B2b_ = (unsigned)__cvta_generic_to_shared(W2st)
                        + (unsigned)((browoff * PADK + bcoloff) * 2);
    const float* bias1 = bstag;
    const float* bias2 = bstag + 128;

    const __nv_bfloat162 C2b[1] = { __float2bfloat162_rn(1.f / 5.f) };
    const __nv_bfloat162 C3b[2] = { __float2bfloat162_rn(3.f / 40.f),
                                    __float2bfloat162_rn(9.f / 40.f) };
    const __nv_bfloat162 C4b[3] = { __float2bfloat162_rn(44.f / 45.f),
                                    __float2bfloat162_rn(-56.f / 15.f),
                                    __float2bfloat162_rn(32.f / 9.f) };
    const __nv_bfloat162 C5b[4] = { __float2bfloat162_rn(19372.f / 6561.f),
                                    __float2bfloat162_rn(-25360.f / 2187.f),
                                    __float2bfloat162_rn(64448.f / 6561.f),
                                    __float2bfloat162_rn(-212.f / 729.f) };
    const __nv_bfloat162 C6b[5] = { __float2bfloat162_rn(9017.f / 3168.f),
                                    __float2bfloat162_rn(-355.f / 33.f),
                                    __float2bfloat162_rn(46732.f / 5247.f),
                                    __float2bfloat162_rn(49.f / 176.f),
                                    __float2bfloat162_rn(-5103.f / 18656.f) };
    const float B1c = 35.f / 384.f, B3c = 500.f / 1113.f, B4c = 125.f / 192.f,
                B5c = -2187.f / 6784.f, B6c = 11.f / 84.f;

    unsigned aH[8][4];
    float c[16][4];
    float tt = 0.f;
    for (int it = 0; it < 48; it++) {
        float dt = fminf(fmaxf(T - tt, 0.f), dt0);
        if (!(dt > 0.f)) break;

#define STAGE(NK, COEF, KQ)                                                  \
        build_arg<NK>(aH, y2, kpb, dt, COEF);                                \
        gemm128(c, aH, B1b_, bias1, qn);                                     \
        /* H = tanh(c) -> A-frags (register identity, no smem) */            \
        _Pragma("unroll")                                                    \
        for (int nt = 0; nt < 16; nt++) {                                    \
            aH[nt >> 1][(nt & 1) * 2 + 0] =                                  \
                tanh_bf2(cvt_bf2u(c[nt][0], c[nt][1]));                      \
            aH[nt >> 1][(nt & 1) * 2 + 1] =                                  \
                tanh_bf2(cvt_bf2u(c[nt][2], c[nt][3]));                      \
        }                                                                    \
        gemm128(c, aH, B2b_, bias2, qn);                                     \
        if (KQ >= 0) {                                                       \
            _Pragma("unroll")                                                \
            for (int nt = 0; nt < 16; nt++)                                  \
                _Pragma("unroll")                                            \
                for (int h = 0; h < 2; h++)                                  \
                    kpb[KQ * 4096 + (nt * 2 + h) * 32] =                     \
                        cvt_bf2u(c[nt][2 * h], c[nt][2 * h + 1]);            \
        }

        STAGE(0, C2b, 0)
        STAGE(1, C2b, 1)
        STAGE(2, C3b, 2)
        STAGE(3, C4b, 3)
        STAGE(4, C5b, 4)
        STAGE(5, C6b, -1)   // c = k6 (fp32 regs)
#undef STAGE

        // y += dt*(B1 k1 + B3 k3 + B4 k4 + B5 k5 + B6 k6)
#pragma unroll
        for (int nt = 0; nt < 16; nt++)
#pragma unroll
            for (int h = 0; h < 2; h++) {
                const int slot = (nt * 2 + h) * 32;
                unsigned k1v = kpb[0 * 4096 + slot];
                unsigned k3v = kpb[2 * 4096 + slot];
                unsigned k4v = kpb[3 * 4096 + slot];
                unsigned k5v = kpb[4 * 4096 + slot];
                float u0 = fmaf(B1c, lo16f(k1v),
                           fmaf(B3c, lo16f(k3v),
                           fmaf(B4c, lo16f(k4v),
                           fmaf(B5c, lo16f(k5v), B6c * c[nt][2 * h]))));
                float u1 = fmaf(B1c, hi16f(k1v),
                           fmaf(B3c, hi16f(k3v),
                           fmaf(B4c, hi16f(k4v),
                           fmaf(B5c, hi16f(k5v), B6c * c[nt][2 * h + 1]))));
                float2 yv = y2[slot];
                yv.x = fmaf(dt, u0, yv.x);
                yv.y = fmaf(dt, u1, yv.y);
                y2[slot] = yv;
            }
        tt += dt;
    }
    __syncthreads();

    // ---- out[1] = yT (coalesced via inverse frag mapping) ----
    for (int idx = tid; idx < 64 * 64; idx += 128) {
        int row = idx >> 6, cp = idx & 63;
        int w = row >> 4, h = (row >> 3) & 1, g = row & 7;
        int nt = cp >> 2, q = cp & 3;
        float2 v = y2all[w * 1024 + (nt * 2 + h) * 32 + g * 4 + q];
        *(float2*)&out[8192 * 128 + (row0 + row) * 128 + cp * 2] = v;
    }
}

// ---------------------------------------------------------------------------
// dt0: faithful fp32 port of initial_step_size on x[0]. (unchanged, proven)
// ---------------------------------------------------------------------------
__device__ __forceinline__ float bsum(float v, float* buf, int j) {
    buf[j] = v; __syncthreads();
    for (int s = 64; s > 0; s >>= 1) { if (j < s) buf[j] += buf[j + s]; __syncthreads(); }
    float r = buf[0]; __syncthreads(); return r;
}
__device__ __forceinline__ void mlp128(const float* yin, float* fout, float* hid,
                                       const float* W1, const float* b1,
                                       const float* W2, const float* b2, int j) {
    float acc = 0.f;
    for (int i = 0; i < 128; i++) acc += yin[i] * W1[i * 128 + j];
    hid[j] = tanhf(acc + b1[j]);
    __syncthreads();
    acc = 0.f;
    for (int i = 0; i < 128; i++) acc += hid[i] * W2[i * 128 + j];
    fout[j] = acc + b2[j];
    __syncthreads();
}
__global__ void dt0_kernel(const float* __restrict__ t, const float* __restrict__ x,
                           const float* __restrict__ W1, const float* __restrict__ b1,
                           const float* __restrict__ W2, const float* __restrict__ b2) {
    __shared__ float y0[128], f0v[128], f1v[128], y1s[128], hid[128], buf[128];
    int j = threadIdx.x;
    y0[j] = x[j];
    __syncthreads();
    mlp128(y0, f0v, hid, W1, b1, W2, b2, j);
    float scale = 1.4e-8f + fabsf(y0[j]) * 1.4e-8f;
    float a0 = y0[j] / scale;
    float d0 = sqrtf(bsum(a0 * a0, buf, j));
    float a1 = f0v[j] / scale;
    float d1 = sqrtf(bsum(a1 * a1, buf, j));
    float h0 = (d0 < 1e-5f || d1 < 1e-5f) ? 1e-6f : (0.01f * d0) / d1;
    y1s[j] = y0[j] + h0 * f0v[j];
    __syncthreads();
    mlp128(y1s, f1v, hid, W1, b1, W2, b2, j);
    float a2 = (f1v[j] - f0v[j]) / scale;
    float d2 = sqrtf(bsum(a2 * a2, buf, j)) / h0;
    float h1 = (d1 <= 1e-15f && d2 <= 1e-15f) ? fmaxf(1e-6f, h0 * 1e-3f)
                                              : powf(0.01f / (d1 + d2), 0.2f);
    if (j == 0) g_dt0 = fminf(100.0f * h0, h1);
}

extern "C" void kernel_launch(void* const* d_in, const int* in_sizes, int n_in,
                              void* d_out, int out_size) {
    const float* t  = (const float*)d_in[0];
    const float* x  = (const float*)d_in[1];
    const float* W1 = (const float*)d_in[2];
    const float* b1 = (const float*)d_in[3];
    const float* W2 = (const float*)d_in[4];
    const float* b2 = (const float*)d_in[5];
    float* out = (float*)d_out;

    dt0_kernel<<<1, 128>>>(t, x, W1, b1, W2, b2);

    int smem = 103424 + 81920;   // weights+bias+y2 | kp[5] = 185344 B
    cudaFuncSetAttribute(ode_kernel, cudaFuncAttributeMaxDynamicSharedMemorySize, smem);
    ode_kernel<<<128, 128, smem>>>(t, x, W1, b1, W2, b2, out);
}

// round 13
// speedup vs baseline: 1.1298x; 1.1298x over previous
#include <cuda_runtime.h>
#include <cuda_bf16.h>

// ---------------------------------------------------------------------------
// NeuralODE Dopri5 fused persistent kernel. R13 = R11 (best, 178.8us) + ONE
// change: a throwaway gemm_w1 prologue for m-group 1 only, skewing the two
// independent 4-warp pipelines by ~half a stage so their GEMM phases
// anti-phase on each SMSP (tensor unit fed ~continuously instead of both
// groups idling it together during elementwise/barrier phases).
// ---------------------------------------------------------------------------

#define PADK 136                       // bf16 row stride (272 B): conflict-free
#define TB   (64 * PADK * 2)           // one 64x128(+pad) bf16 tile = 17408 B
typedef __nv_bfloat16 Row[PADK];

__device__ float g_dt0;

__device__ __forceinline__ unsigned cvt_bf2u(float lo, float hi) {
    unsigned r; asm("cvt.rn.bf16x2.f32 %0, %1, %2;" : "=r"(r) : "f"(hi), "f"(lo)); return r;
}
__device__ __forceinline__ unsigned tanh_bf2(unsigned p) {
    unsigned r; asm("tanh.approx.bf16x2 %0, %1;" : "=r"(r) : "r"(p)); return r;
}
__device__ __forceinline__ float lo16f(unsigned u) { return __uint_as_float(u << 16); }
__device__ __forceinline__ float hi16f(unsigned u) { return __uint_as_float(u & 0xFFFF0000u); }
__device__ __forceinline__ __nv_bfloat162 asbf2(unsigned u) {
    return *reinterpret_cast<__nv_bfloat162*>(&u);
}
__device__ __forceinline__ void mma_bf16(float* c, const unsigned* a, const unsigned* b) {
    asm volatile("mma.sync.aligned.m16n8k16.row.col.f32.bf16.bf16.f32 "
                 "{%0,%1,%2,%3}, {%4,%5,%6,%7}, {%8,%9}, {%0,%1,%2,%3};"
                 : "+f"(c[0]), "+f"(c[1]), "+f"(c[2]), "+f"(c[3])
                 : "r"(a[0]), "r"(a[1]), "r"(a[2]), "r"(a[3]), "r"(b[0]), "r"(b[1]));
}
__device__ __forceinline__ void ldsm_x4(unsigned a[4], unsigned addr) {
    asm volatile("ldmatrix.sync.aligned.m8n8.x4.shared.b16 {%0,%1,%2,%3}, [%4];"
                 : "=r"(a[0]), "=r"(a[1]), "=r"(a[2]), "=r"(a[3]) : "r"(addr));
}

// GEMM1: C[32x32] = A[32x128] @ W1t^T + b1. B from registers, bias from smem.
__device__ __forceinline__ void gemm_w1(float c[2][4][4], unsigned abase,
                                        const unsigned (&wb)[4][8][2],
                                        const float* bias, int n0, int qn) {
#pragma unroll
    for (int nt = 0; nt < 4; nt++) {
        const int nb = n0 + nt * 8 + qn * 2;
        float b0 = bias[nb], b1v = bias[nb + 1];
#pragma unroll
        for (int mt = 0; mt < 2; mt++) {
            c[mt][nt][0] = c[mt][nt][2] = b0;
            c[mt][nt][1] = c[mt][nt][3] = b1v;
        }
    }
#pragma unroll
    for (int kk = 0; kk < 8; kk++) {
        unsigned a[2][4];
#pragma unroll
        for (int mt = 0; mt < 2; mt++)
            ldsm_x4(a[mt], abase + mt * (16 * PADK * 2) + kk * 32);
#pragma unroll
        for (int mt = 0; mt < 2; mt++)
#pragma unroll
            for (int nt = 0; nt < 4; nt++)
                mma_bf16(c[mt][nt], a[mt], wb[nt][kk]);
    }
}

// GEMM2: C = H @ W2t^T + b2. B via two ldmatrix.x4 per kk, bias from smem.
__device__ __forceinline__ void gemm_w2(float c[2][4][4], unsigned abase,
                                        unsigned bw0, unsigned bw1,
                                        const float* bias, int n0, int qn) {
#pragma unroll
    for (int nt = 0; nt < 4; nt++) {
        const int nb = n0 + nt * 8 + qn * 2;
        float b0 = bias[nb], b1v = bias[nb + 1];
#pragma unroll
        for (int mt = 0; mt < 2; mt++) {
            c[mt][nt][0] = c[mt][nt][2] = b0;
            c[mt][nt][1] = c[mt][nt][3] = b1v;
        }
    }
#pragma unroll
    for (int kk = 0; kk < 8; kk++) {
        unsigned a[2][4], b0[4], b1[4];
#pragma unroll
        for (int mt = 0; mt < 2; mt++)
            ldsm_x4(a[mt], abase + mt * (16 * PADK * 2) + kk * 32);
        ldsm_x4(b0, bw0 + kk * 32);
        ldsm_x4(b1, bw1 + kk * 32);
#pragma unroll
        for (int mt = 0; mt < 2; mt++) {
            mma_bf16(c[mt][0], a[mt], b0);
            mma_bf16(c[mt][1], a[mt], b0 + 2);
            mma_bf16(c[mt][2], a[mt], b1);
            mma_bf16(c[mt][3], a[mt], b1 + 2);
        }
    }
}

// Stage arg: Abuf = bf16(y + dt * sum_q kc[q]*k_q); k's from packed registers.
template <int NK>
__device__ __forceinline__ void build_arg(Row* Abuf, const unsigned (&kp)[5][16],
                                          const float (&y)[2][4][4],
                                          float dt, const __nv_bfloat162* kc,
                                          int m0, int n0, int gm, int qn) {
#pragma unroll
    for (int mt = 0; mt < 2; mt++)
#pragma unroll
        for (int nt = 0; nt < 4; nt++)
#pragma unroll
            for (int h = 0; h < 2; h++) {
                const int id = (mt * 4 + nt) * 2 + h;
                const int r = m0 + mt * 16 + gm + 8 * h;
                const int n = n0 + nt * 8 + qn * 2;
                unsigned v;
                if (NK == 0) {
                    v = cvt_bf2u(y[mt][nt][2 * h], y[mt][nt][2 * h + 1]);
                } else {
                    __nv_bfloat162 acc = __hmul2(asbf2(kp[0][id]), kc[0]);
#pragma unroll
                    for (int q = 1; q < NK; q++)
                        acc = __hfma2(asbf2(kp[q][id]), kc[q], acc);
                    unsigned au = *reinterpret_cast<unsigned*>(&acc);
                    float a0 = fmaf(dt, lo16f(au), y[mt][nt][2 * h]);
                    float a1 = fmaf(dt, hi16f(au), y[mt][nt][2 * h + 1]);
                    v = cvt_bf2u(a0, a1);
                }
                *(unsigned*)&Abuf[r][n] = v;
            }
}

// pack first, ONE tanh.approx.bf16x2 per pair.
__device__ __forceinline__ void store_h(Row* dst, const float c[2][4][4],
                                        int m0, int n0, int gm, int qn) {
#pragma unroll
    for (int mt = 0; mt < 2; mt++)
#pragma unroll
        for (int nt = 0; nt < 4; nt++) {
            const int r = m0 + mt * 16 + gm;
            const int n = n0 + nt * 8 + qn * 2;
            *(unsigned*)&dst[r][n] =
                tanh_bf2(cvt_bf2u(c[mt][nt][0], c[mt][nt][1]));
            *(unsigned*)&dst[r + 8][n] =
                tanh_bf2(cvt_bf2u(c[mt][nt][2], c[mt][nt][3]));
        }
}

__global__ void __launch_bounds__(256, 1)
ode_kernel(const float* __restrict__ t, const float* __restrict__ x,
           const float* __restrict__ W1, const float* __restrict__ b1,
           const float* __restrict__ W2, const float* __restrict__ b2,
           float* __restrict__ out) {
    extern __shared__ unsigned char raw[];
    // smem: Abuf0 | Abuf1 | Hbuf0 | Hbuf1 | Wt2 | bstag
    Row* Abufs[2] = { (Row*)(raw + 0 * TB), (Row*)(raw + 1 * TB) };
    Row* Hbufs[2] = { (Row*)(raw + 2 * TB), (Row*)(raw + 3 * TB) };
    Row* Wst2 = (Row*)(raw + 4 * TB);                      // permanent
    float* bstag = (float*)(raw + 4 * TB + 128 * PADK * 2);// 256 floats
    Row* Wst = (Row*)raw;                                  // W1 staging (dead later)

    const int tid  = threadIdx.x;
    const int row0 = blockIdx.x * 64;
    const int lane = tid & 31, warp = tid >> 5;
    const int m0 = (warp & 1) * 32;        // R9/R11 mapping (best)
    const int n0 = (warp >> 1) * 32;       // 4 n-positions
    const int gm = lane >> 2;              // 0..7
    const int qn = lane & 3;               // 0..3
    const int barid = 1 + (warp & 1);      // named barrier per m-group (4 warps)
    const int lrow = lane & 15;
    const int lcol = (lane >> 4) * 8;

#define BARG() asm volatile("bar.sync %0, 128;" :: "r"(barid) : "memory")

    // ---- stage W1 (transposed) into tiles 0-1; W2 into permanent Wt2 ----
    for (int idx = tid; idx < 128 * 128; idx += 256) {
        int k = idx >> 7, n = idx & 127;
        Wst[n][k]  = __float2bfloat16(W1[idx]);
        Wst2[n][k] = __float2bfloat16(W2[idx]);
    }
    if (tid < 128) { bstag[tid] = b1[tid]; bstag[128 + tid] = b2[tid]; }
    for (int idx = tid; idx < 64 * 128; idx += 256)
        out[row0 * 128 + idx] = x[row0 * 128 + idx];
    __syncthreads();

    // ---- W1 B-fragments -> registers (64 regs) ----
    unsigned wb1[4][8][2];
#pragma unroll
    for (int nt = 0; nt < 4; nt++) {
        const int n = n0 + nt * 8 + gm;
#pragma unroll
        for (int kk = 0; kk < 8; kk++) {
            const int kb = kk * 16 + qn * 2;
            wb1[nt][kk][0] = *(const unsigned*)&Wst[n][kb];
            wb1[nt][kk][1] = *(const unsigned*)&Wst[n][kb + 8];
        }
    }

    // ---- state y -> registers (C-fragment layout) ----
    float yreg[2][4][4];
    {
        const float* xr = x + row0 * 128;
#pragma unroll
        for (int mt = 0; mt < 2; mt++)
#pragma unroll
            for (int nt = 0; nt < 4; nt++)
#pragma unroll
                for (int h = 0; h < 2; h++) {
                    const int r = m0 + mt * 16 + gm + 8 * h;
                    const int n = n0 + nt * 8 + qn * 2;
                    float2 v = *(const float2*)&xr[r * 128 + n];
                    yreg[mt][nt][2 * h]     = v.x;
                    yreg[mt][nt][2 * h + 1] = v.y;
                }
    }
    __syncthreads();   // W1 staging dead; Abuf/Hbuf writable

    const float T   = t[0] / 10.0f;    // TIMESCALE = 10
    const float dt0 = g_dt0;

    const unsigned aoff = (unsigned)(((m0 + lrow) * PADK + lcol) * 2);
    const unsigned Ab[2] = { (unsigned)__cvta_generic_to_shared(Abufs[0]) + aoff,
                             (unsigned)__cvta_generic_to_shared(Abufs[1]) + aoff };
    const unsigned Hb[2] = { (unsigned)__cvta_generic_to_shared(Hbufs[0]) + aoff,
                             (unsigned)__cvta_generic_to_shared(Hbufs[1]) + aoff };
    const int browoff = (lane & 7) + ((lane >> 4) << 3);
    const int bcoloff = ((lane >> 3) & 1) * 8;
    const unsigned Bw0 = (unsigned)__cvta_generic_to_shared(Wst2)
                       + (unsigned)(((n0 + browoff) * PADK + bcoloff) * 2);
    const unsigned Bw1 = Bw0 + 16 * PADK * 2;
    const float* bias1 = bstag;
    const float* bias2 = bstag + 128;

    const __nv_bfloat162 C2b[1] = { __float2bfloat162_rn(1.f / 5.f) };
    const __nv_bfloat162 C3b[2] = { __float2bfloat162_rn(3.f / 40.f),
                                    __float2bfloat162_rn(9.f / 40.f) };
    const __nv_bfloat162 C4b[3] = { __float2bfloat162_rn(44.f / 45.f),
                                    __float2bfloat162_rn(-56.f / 15.f),
                                    __float2bfloat162_rn(32.f / 9.f) };
    const __nv_bfloat162 C5b[4] = { __float2bfloat162_rn(19372.f / 6561.f),
                                    __float2bfloat162_rn(-25360.f / 2187.f),
                                    __float2bfloat162_rn(64448.f / 6561.f),
                                    __float2bfloat162_rn(-212.f / 729.f) };
    const __nv_bfloat162 C6b[5] = { __float2bfloat162_rn(9017.f / 3168.f),
                                    __float2bfloat162_rn(-355.f / 33.f),
                                    __float2bfloat162_rn(46732.f / 5247.f),
                                    __float2bfloat162_rn(49.f / 176.f),
                                    __float2bfloat162_rn(-5103.f / 18656.f) };
    const float B1 = 35.f / 384.f, B3 = 500.f / 1113.f, B4 = 125.f / 192.f,
                B5 = -2187.f / 6784.f, B6 = 11.f / 84.f;

    unsigned kp[5][16];                 // k1..k5 packed bf16x2, own 32x32 tile
    float c[2][4][4];

    // ---- R13: phase-skew prologue. m-group 1 burns ~one GEMM of time on a
    // throwaway gemm_w1 (deterministic staging bytes, result discarded) so
    // the two independent group pipelines run anti-phased on each SMSP and
    // the tensor units see MMA work ~continuously. Reads rows 32-63 only
    // (group-1 rows); any raced values are discarded -> correctness intact.
    if (m0 != 0) {
        gemm_w1(c, Ab[0], wb1, bias1, n0, qn);
    }

    float tt = 0.f;
    int p = 0;
    for (int it = 0; it < 48; it++) {
        float dt = fminf(fmaxf(T - tt, 0.f), dt0);
        if (!(dt > 0.f)) break;

#define STAGE(NK, COEF, KQ)                                                  \
        build_arg<NK>(Abufs[p], kp, yreg, dt, COEF, m0, n0, gm, qn);         \
        BARG();                          /* Abuf[p] ready (m-group) */       \
        gemm_w1(c, Ab[p], wb1, bias1, n0, qn);                               \
        store_h(Hbufs[p], c, m0, n0, gm, qn);                                \
        BARG();                          /* Hbuf[p] ready; Abuf[p] free */   \
        gemm_w2(c, Hb[p], Bw0, Bw1, bias2, n0, qn);                          \
        if (KQ >= 0) {                                                       \
            _Pragma("unroll")                                                \
            for (int mt = 0; mt < 2; mt++)                                   \
                _Pragma("unroll")                                            \
                for (int nt = 0; nt < 4; nt++)                               \
                    _Pragma("unroll")                                        \
                    for (int h = 0; h < 2; h++)                              \
                        kp[KQ][(mt * 4 + nt) * 2 + h] =                      \
                            cvt_bf2u(c[mt][nt][2 * h], c[mt][nt][2 * h + 1]);\
        }                                                                    \
        p ^= 1;

        STAGE(0, C2b, 0)
        STAGE(1, C2b, 1)
        STAGE(2, C3b, 2)
        STAGE(3, C4b, 3)
        STAGE(4, C5b, 4)
        STAGE(5, C6b, -1)   // c = k6, stays fp32 in registers
#undef STAGE

        // y += dt*(B1 k1 + B3 k3 + B4 k4 + B5 k5 + B6 k6)  (fp32 math)
#pragma unroll
        for (int mt = 0; mt < 2; mt++)
#pragma unroll
            for (int nt = 0; nt < 4; nt++)
#pragma unroll
                for (int h = 0; h < 2; h++) {
                    const int id = (mt * 4 + nt) * 2 + h;
                    float u0 = fmaf(B1, lo16f(kp[0][id]),
                               fmaf(B3, lo16f(kp[2][id]),
                               fmaf(B4, lo16f(kp[3][id]),
                               fmaf(B5, lo16f(kp[4][id]),
                                    B6 * c[mt][nt][2 * h]))));
                    float u1 = fmaf(B1, hi16f(kp[0][id]),
                               fmaf(B3, hi16f(kp[2][id]),
                               fmaf(B4, hi16f(kp[3][id]),
                               fmaf(B5, hi16f(kp[4][id]),
                                    B6 * c[mt][nt][2 * h + 1]))));
                    yreg[mt][nt][2 * h]     = fmaf(dt, u0, yreg[mt][nt][2 * h]);
                    yreg[mt][nt][2 * h + 1] = fmaf(dt, u1, yreg[mt][nt][2 * h + 1]);
                }
        tt += dt;
    }

    // ---- out[1] = yT ----
    float* o1 = out + 8192 * 128 + row0 * 128;
#pragma unroll
    for (int mt = 0; mt < 2; mt++)
#pragma unroll
        for (int nt = 0; nt < 4; nt++)
#pragma unroll
            for (int h = 0; h < 2; h++) {
                const int r = m0 + mt * 16 + gm + 8 * h;
                const int n = n0 + nt * 8 + qn * 2;
                float2 v;
                v.x = yreg[mt][nt][2 * h];
                v.y = yreg[mt][nt][2 * h + 1];
                *(float2*)&o1[r * 128 + n] = v;
            }
#undef BARG
}

// ---------------------------------------------------------------------------
// dt0: faithful fp32 port of initial_step_size on x[0]. (unchanged, proven)
// ---------------------------------------------------------------------------
__device__ __forceinline__ float bsum(float v, float* buf, int j) {
    buf[j] = v; __syncthreads();
    for (int s = 64; s > 0; s >>= 1) { if (j < s) buf[j] += buf[j + s]; __syncthreads(); }
    float r = buf[0]; __syncthreads(); return r;
}
__device__ __forceinline__ void mlp128(const float* yin, float* fout, float* hid,
                                       const float* W1, const float* b1,
                                       const float* W2, const float* b2, int j) {
    float acc = 0.f;
    for (int i = 0; i < 128; i++) acc += yin[i] * W1[i * 128 + j];
    hid[j] = tanhf(acc + b1[j]);
    __syncthreads();
    acc = 0.f;
    for (int i = 0; i < 128; i++) acc += hid[i] * W2[i * 128 + j];
    fout[j] = acc + b2[j];
    __syncthreads();
}
__global__ void dt0_kernel(const float* __restrict__ t, const float* __restrict__ x,
                           const float* __restrict__ W1, const float* __restrict__ b1,
                           const float* __restrict__ W2, const float* __restrict__ b2) {
    __shared__ float y0[128], f0v[128], f1v[128], y1s[128], hid[128], buf[128];
    int j = threadIdx.x;
    y0[j] = x[j];
    __syncthreads();
    mlp128(y0, f0v, hid, W1, b1, W2, b2, j);
    float scale = 1.4e-8f + fabsf(y0[j]) * 1.4e-8f;
    float a0 = y0[j] / scale;
    float d0 = sqrtf(bsum(a0 * a0, buf, j));
    float a1 = f0v[j] / scale;
    float d1 = sqrtf(bsum(a1 * a1, buf, j));
    float h0 = (d0 < 1e-5f || d1 < 1e-5f) ? 1e-6f : (0.01f * d0) / d1;
    y1s[j] = y0[j] + h0 * f0v[j];
    __syncthreads();
    mlp128(y1s, f1v, hid, W1, b1, W2, b2, j);
    float a2 = (f1v[j] - f0v[j]) / scale;
    float d2 = sqrtf(bsum(a2 * a2, buf, j)) / h0;
    float h1 = (d1 <= 1e-15f && d2 <= 1e-15f) ? fmaxf(1e-6f, h0 * 1e-3f)
                                              : powf(0.01f / (d1 + d2), 0.2f);
    if (j == 0) g_dt0 = fminf(100.0f * h0, h1);
}

extern "C" void kernel_launch(void* const* d_in, const int* in_sizes, int n_in,
                              void* d_out, int out_size) {
    const float* t  = (const float*)d_in[0];
    const float* x  = (const float*)d_in[1];
    const float* W1 = (const float*)d_in[2];
    const float* b1 = (const float*)d_in[3];
    const float* W2 = (const float*)d_in[4];
    const float* b2 = (const float*)d_in[5];
    float* out = (float*)d_out;

    dt0_kernel<<<1, 128>>>(t, x, W1, b1, W2, b2);

    int smem = 4 * TB + 128 * PADK * 2 + 1024;   // 4 tiles + Wt2 + bstag = 105472 B
    cudaFuncSetAttribute(ode_kernel, cudaFuncAttributeMaxDynamicSharedMemorySize, smem);
    ode_kernel<<<128, 256, smem>>>(t, x, W1, b1, W2, b2, out);
}